// round 14
// baseline (speedup 1.0000x reference)
#include <cuda_runtime.h>
#include <math.h>
#include <stdint.h>

#define DIM_  1024
#define DIN_  1536
#define B_    4
#define L_    4096
#define M_    (B_ * L_)          // 16384
#define NCHUNK_ 32
#define CHUNK_  (L_ / NCHUNK_)   // 128

// ---------------- static scratch (no allocations allowed) ----------------
__device__ __align__(16) float  g_xz[(size_t)M_ * 2 * DIN_];  // in_proj out [M,3072]
__device__ __align__(16) float  g_dt[(size_t)M_ * DIN_];
__device__ __align__(16) float  g_yf[(size_t)M_ * DIN_];      // y fp32 before quant
// int8 limb arrays + per-row scales
__device__ __align__(16) int8_t g_xq0[(size_t)M_ * DIM_];
__device__ __align__(16) int8_t g_xq1[(size_t)M_ * DIM_];
__device__ __align__(16) int8_t g_wiq0[(size_t)2 * DIN_ * DIM_];
__device__ __align__(16) int8_t g_wiq1[(size_t)2 * DIN_ * DIM_];
__device__ __align__(16) int8_t g_dwq0[(size_t)DIN_ * DIN_];
__device__ __align__(16) int8_t g_dwq1[(size_t)DIN_ * DIN_];
__device__ __align__(16) int8_t g_woq0[(size_t)DIM_ * DIN_];
__device__ __align__(16) int8_t g_woq1[(size_t)DIM_ * DIN_];
__device__ __align__(16) int8_t g_xcq0[(size_t)M_ * DIN_];
__device__ __align__(16) int8_t g_xcq1[(size_t)M_ * DIN_];
__device__ __align__(16) int8_t g_yq0[(size_t)M_ * DIN_];
__device__ __align__(16) int8_t g_yq1[(size_t)M_ * DIN_];
__device__ float g_sx[M_];
__device__ float g_swi[2 * DIN_];
__device__ float g_sdw[DIN_];
__device__ float g_swo[DIM_];
__device__ float g_sxc[M_];
__device__ float g_sy[M_];
__device__ float g_csum[B_ * NCHUNK_ * DIN_];
__device__ float g_cpre[B_ * NCHUNK_ * DIN_];

__device__ __forceinline__ float softplus_f(float v) {
    return v > 20.f ? v : log1pf(expf(v));
}
__device__ __forceinline__ float silu_f(float v) {
    return v / (1.f + expf(-v));
}
__device__ __forceinline__ float deq_f(int8_t q0, int8_t q1, float s) {
    return s * fmaf((float)q1, 0.0078125f, (float)q0);
}
// 2-limb int8 quantization: v = s*(a0 + a1/128), |a0|<=127, |a1|<=64
__device__ __forceinline__ void quant2(float v, float inv, int8_t& a0, int8_t& a1) {
    float q  = v * inv;
    float f0 = rintf(q);
    float f1 = rintf((q - f0) * 128.f);
    a0 = (int8_t)(int)f0;
    a1 = (int8_t)(int)f1;
}

// ======================= PTX helpers (base sm_90+/sm_103) =======================
__device__ __forceinline__ uint32_t smem_u32(const void* p) {
    uint32_t a;
    asm("{ .reg .u64 t; cvta.to.shared.u64 t, %1; cvt.u32.u64 %0, t; }" : "=r"(a) : "l"(p));
    return a;
}
#define CP16(saddr, gptr) \
    asm volatile("cp.async.cg.shared.global [%0], [%1], 16;" :: "r"(saddr), "l"(gptr))

#define MBAR_INIT(addr, cnt) \
    asm volatile("mbarrier.init.shared.b64 [%0], %1;" :: "r"(addr), "r"(cnt) : "memory")
#define MBAR_ARRIVE(addr) \
    asm volatile("mbarrier.arrive.shared.b64 _, [%0];" :: "r"(addr) : "memory")
#define CPA_ARRIVE(addr) \
    asm volatile("cp.async.mbarrier.arrive.noinc.shared.b64 [%0];" :: "r"(addr) : "memory")
#define MBAR_WAIT(addr, ph) do {                                                   \
    uint32_t _m = (addr); uint32_t _p = (ph); uint32_t _d;                         \
    asm volatile("{ .reg .pred p; mbarrier.try_wait.parity.acquire.cta.shared::cta.b64 p, [%1], %2; selp.b32 %0,1,0,p; }" \
        : "=r"(_d) : "r"(_m), "r"(_p) : "memory");                                 \
    if (!_d) {                                                                     \
        asm volatile("{ .reg .pred P1; WL%=: mbarrier.try_wait.parity.acquire.cta.shared::cta.b64 P1, [%0], %1, 0x989680; @P1 bra.uni WD%=; bra.uni WL%=; WD%=: }" \
            :: "r"(_m), "r"(_p) : "memory");                                       \
    } } while (0)

#define LDSM4(r, a) \
    asm volatile("ldmatrix.sync.aligned.m8n8.x4.shared.b16 {%0,%1,%2,%3}, [%4];" \
        : "=r"((r)[0]), "=r"((r)[1]), "=r"((r)[2]), "=r"((r)[3]) : "r"(a))

#define MMA_S8(d, a, b0v, b1v) \
    asm volatile("mma.sync.aligned.m16n8k32.row.col.s32.s8.s8.s32 " \
        "{%0,%1,%2,%3}, {%4,%5,%6,%7}, {%8,%9}, {%0,%1,%2,%3};" \
        : "+r"((d)[0]), "+r"((d)[1]), "+r"((d)[2]), "+r"((d)[3]) \
        : "r"((a)[0]), "r"((a)[1]), "r"((a)[2]), "r"((a)[3]), "r"(b0v), "r"(b1v))

__device__ __forceinline__ uint32_t sw64(uint32_t off) {
    return off ^ ((off >> 3) & 0x30);
}

// ======================= 2-limb int8 IMMA GEMM =======================
// C[m,n] = sA[m]*sB[n] * (P00 + (P01+P10)/128), limbs K-contiguous int8.
// Block 128(M)x64(N), BK=64, 256 threads (8 warps: 4M x 2N, warp tile 32x32).
// 4-stage mbarrier pipeline, 2 CTAs/SM.
#define BK8_     64
#define STAGE8_B 24576          // A0 8K | A1 8K | B0 4K | B1 4K
#define A1_OFF   8192
#define B0_OFF   16384
#define B1_OFF   20480
#define GEMM8_SMEM (4 * STAGE8_B)   // 96 KB

__device__ __forceinline__ void load_stage_s8(
    uint32_t sb, const int8_t* __restrict__ A0, const int8_t* __restrict__ A1,
    const int8_t* __restrict__ B0, const int8_t* __restrict__ B1,
    int row0, int col0, int k0, int K, int tid)
{
#pragma unroll
    for (int i = 0; i < 2; ++i) {
        const int idx = tid + i * 256;          // 0..511
        const int r  = idx >> 2;                // 0..127
        const int kg = idx & 3;                 // 16B group along K(64B row)
        const uint32_t so = sw64((uint32_t)(r * 64 + kg * 16));
        const size_t g = (size_t)(row0 + r) * K + k0 + kg * 16;
        CP16(sb + so,          A0 + g);
        CP16(sb + A1_OFF + so, A1 + g);
    }
    {
        const int r  = tid >> 2;                // 0..63
        const int kg = tid & 3;
        const uint32_t so = sw64((uint32_t)(r * 64 + kg * 16));
        const size_t g = (size_t)(col0 + r) * K + k0 + kg * 16;
        CP16(sb + B0_OFF + so, B0 + g);
        CP16(sb + B1_OFF + so, B1 + g);
    }
}

// MODE 0: plain store.  MODE 1: softplus(acc + bias[n]).
template <int MODE>
__global__ void __launch_bounds__(256, 2)
s8_gemm(const int8_t* __restrict__ A0, const int8_t* __restrict__ A1,
        const float* __restrict__ sA,
        const int8_t* __restrict__ B0, const int8_t* __restrict__ B1,
        const float* __restrict__ sB,
        float* __restrict__ C, const float* __restrict__ bias,
        int M, int N, int K)
{
    extern __shared__ char smem_raw[];
    __shared__ __align__(8) uint64_t s_mbar[8];   // full[4], empty[4]
    const uint32_t smb = smem_u32(smem_raw);
    const int tid  = threadIdx.x;
    const int lane = tid & 31;
    const int wid  = tid >> 5;
    const int wm   = (wid >> 1) * 32;   // 4 M groups
    const int wn   = (wid & 1) * 32;    // 2 N groups
    const int row0 = blockIdx.y * 128;
    const int col0 = blockIdx.x * 64;
    const int nch  = K / BK8_;          // 16 or 24, divisible by 4

    if (tid == 0) {
#pragma unroll
        for (int s = 0; s < 8; ++s) MBAR_INIT(smem_u32(&s_mbar[s]), 256);
    }
    __syncthreads();

    int acc00[2][4][4], accX[2][4][4];
#pragma unroll
    for (int i = 0; i < 2; ++i)
#pragma unroll
        for (int j = 0; j < 4; ++j)
#pragma unroll
            for (int t = 0; t < 4; ++t) { acc00[i][j][t] = 0; accX[i][j][t] = 0; }

    // prologue: fill all 4 stages with chunks 0..3
#pragma unroll
    for (int h = 0; h < 4; ++h) {
        load_stage_s8(smb + h * STAGE8_B, A0, A1, B0, B1, row0, col0, h * BK8_, K, tid);
        CPA_ARRIVE(smem_u32(&s_mbar[h]));
    }

    // hoisted per-lane ldmatrix tile-local swizzled offsets
    const int a_row = (lane & 7) + ((lane >> 3) & 1) * 8;
    const int a_kof = ((lane >> 4) & 1) * 16;
    const int b_row = (lane & 7) + ((lane >> 4) & 1) * 8;
    const int b_kof = ((lane >> 3) & 1) * 16;
    uint32_t offA[2][2], offB[2][2];
#pragma unroll
    for (int ks = 0; ks < 2; ++ks) {
#pragma unroll
        for (int mt = 0; mt < 2; ++mt)
            offA[ks][mt] = sw64((uint32_t)((wm + mt * 16 + a_row) * 64 + ks * 32 + a_kof));
#pragma unroll
        for (int np = 0; np < 2; ++np)
            offB[ks][np] = B0_OFF +
                sw64((uint32_t)((wn + np * 16 + b_row) * 64 + ks * 32 + b_kof));
    }

    const int T = nch >> 2;
    for (int t = 0; t < T; ++t) {
        const uint32_t par = (uint32_t)(t & 1);
#pragma unroll
        for (int h = 0; h < 4; ++h) {
            const uint32_t sb  = smb + h * STAGE8_B;
            const uint32_t mbf = smem_u32(&s_mbar[h]);
            const uint32_t mbe = smem_u32(&s_mbar[4 + h]);

            MBAR_WAIT(mbf, par);
#pragma unroll
            for (int ks = 0; ks < 2; ++ks) {
                uint32_t fB0[2][4], fB1[2][4];
#pragma unroll
                for (int np = 0; np < 2; ++np) {
                    LDSM4(fB0[np], sb + offB[ks][np]);
                    LDSM4(fB1[np], sb + offB[ks][np] + (B1_OFF - B0_OFF));
                }
#pragma unroll
                for (int mt = 0; mt < 2; ++mt) {
                    uint32_t fA0[4], fA1[4];
                    LDSM4(fA0, sb + offA[ks][mt]);
                    LDSM4(fA1, sb + offA[ks][mt] + A1_OFF);
                    if (ks == 1 && mt == 1) MBAR_ARRIVE(mbe);
                    // class-major order: dependent IMMAs 4 apart
#pragma unroll
                    for (int nt = 0; nt < 4; ++nt) {
                        const int np = nt >> 1, rr = (nt & 1) * 2;
                        MMA_S8(acc00[mt][nt], fA0, fB0[np][rr], fB0[np][rr + 1]);
                    }
#pragma unroll
                    for (int nt = 0; nt < 4; ++nt) {
                        const int np = nt >> 1, rr = (nt & 1) * 2;
                        MMA_S8(accX[mt][nt], fA0, fB1[np][rr], fB1[np][rr + 1]);
                    }
#pragma unroll
                    for (int nt = 0; nt < 4; ++nt) {
                        const int np = nt >> 1, rr = (nt & 1) * 2;
                        MMA_S8(accX[mt][nt], fA1, fB0[np][rr], fB0[np][rr + 1]);
                    }
                }
            }
            if (t < T - 1) {
                MBAR_WAIT(mbe, par);
                load_stage_s8(sb, A0, A1, B0, B1, row0, col0,
                              (4 * t + h + 4) * BK8_, K, tid);
                CPA_ARRIVE(mbf);
            }
        }
    }

    // epilogue: dequant + store
#pragma unroll
    for (int mt = 0; mt < 2; ++mt) {
        const int r0 = row0 + wm + mt * 16 + (lane >> 2);
        const float sa0 = __ldg(&sA[r0]);
        const float sa8 = __ldg(&sA[r0 + 8]);
#pragma unroll
        for (int nt = 0; nt < 4; ++nt) {
            const int cc = col0 + wn + nt * 8 + (lane & 3) * 2;
            const float sb0 = __ldg(&sB[cc]);
            const float sb1 = __ldg(&sB[cc + 1]);
            float v0 = fmaf((float)accX[mt][nt][0], 0.0078125f, (float)acc00[mt][nt][0]) * sa0 * sb0;
            float v1 = fmaf((float)accX[mt][nt][1], 0.0078125f, (float)acc00[mt][nt][1]) * sa0 * sb1;
            float v2 = fmaf((float)accX[mt][nt][2], 0.0078125f, (float)acc00[mt][nt][2]) * sa8 * sb0;
            float v3 = fmaf((float)accX[mt][nt][3], 0.0078125f, (float)acc00[mt][nt][3]) * sa8 * sb1;
            if (MODE == 1) {
                const float b0 = __ldg(&bias[cc]), b1 = __ldg(&bias[cc + 1]);
                v0 = softplus_f(v0 + b0); v1 = softplus_f(v1 + b1);
                v2 = softplus_f(v2 + b0); v3 = softplus_f(v3 + b1);
            }
            *(float2*)&C[(size_t)r0 * N + cc]       = make_float2(v0, v1);
            *(float2*)&C[(size_t)(r0 + 8) * N + cc] = make_float2(v2, v3);
        }
    }
}

// ---------------- block max reduce (256 threads) -------------------------
__device__ __forceinline__ float block_max256(float m) {
    __shared__ float red[8];
#pragma unroll
    for (int o = 16; o; o >>= 1) m = fmaxf(m, __shfl_xor_sync(0xFFFFFFFFu, m, o));
    if ((threadIdx.x & 31) == 0) red[threadIdx.x >> 5] = m;
    __syncthreads();
    float r = red[0];
#pragma unroll
    for (int i = 1; i < 8; ++i) r = fmaxf(r, red[i]);
    return r;
}

// ---------------- per-row 2-limb quantization ----------------------------
template <int NE>   // elements per thread; K = NE*256
__global__ void __launch_bounds__(256)
quant_rows(const float* __restrict__ src, int8_t* __restrict__ q0,
           int8_t* __restrict__ q1, float* __restrict__ scale)
{
    const int K = NE * 256;
    const int row = blockIdx.x;
    const int tid = threadIdx.x;
    const float* s = src + (size_t)row * K;
    float v[NE];
    float m = 0.f;
#pragma unroll
    for (int i = 0; i < NE; ++i) {
        v[i] = s[tid + i * 256];
        m = fmaxf(m, fabsf(v[i]));
    }
    m = block_max256(m);
    const float sc  = (m > 0.f) ? m / 127.f : 1.f;
    const float inv = (m > 0.f) ? 127.f / m : 0.f;
#pragma unroll
    for (int i = 0; i < NE; ++i) {
        int8_t a0, a1;
        quant2(v[i], inv, a0, a1);
        q0[(size_t)row * K + tid + i * 256] = a0;
        q1[(size_t)row * K + tid + i * 256] = a1;
    }
    if (tid == 0) scale[row] = sc;
}

// ---------------- depthwise conv3 + bias + SiLU + per-row quant -----------
__global__ void __launch_bounds__(256)
conv_silu_quant(const float* __restrict__ cw, const float* __restrict__ cb)
{
    const int row = blockIdx.x;           // bl index, 0..M_-1
    const int l   = row & (L_ - 1);
    const int tid = threadIdx.x;
    const float* base = g_xz + (size_t)row * (2 * DIN_);
    float v[6];
    float m = 0.f;
#pragma unroll
    for (int i = 0; i < 6; ++i) {
        const int c = tid + i * 256;
        float x0 = base[c];
        float xm = (l > 0)      ? base[c - 2 * DIN_] : 0.f;
        float xp = (l < L_ - 1) ? base[c + 2 * DIN_] : 0.f;
        float w0 = __ldg(&cw[c * 3 + 0]);
        float w1 = __ldg(&cw[c * 3 + 1]);
        float w2 = __ldg(&cw[c * 3 + 2]);
        float t = fmaf(w0, xm, fmaf(w1, x0, fmaf(w2, xp, __ldg(&cb[c]))));
        v[i] = silu_f(t);
        m = fmaxf(m, fabsf(v[i]));
    }
    m = block_max256(m);
    const float sc  = (m > 0.f) ? m / 127.f : 1.f;
    const float inv = (m > 0.f) ? 127.f / m : 0.f;
#pragma unroll
    for (int i = 0; i < 6; ++i) {
        const int c = tid + i * 256;
        int8_t a0, a1;
        quant2(v[i], inv, a0, a1);
        g_xcq0[(size_t)row * DIN_ + c] = a0;
        g_xcq1[(size_t)row * DIN_ + c] = a1;
    }
    if (tid == 0) g_sxc[row] = sc;
}

// ---------------- scan phase 1: per-chunk sums ----------------------------
__global__ void __launch_bounds__(256)
scan_phase1(const float* __restrict__ Aw)
{
    const int ct = blockIdx.y % (DIN_ / 256);
    const int b  = blockIdx.y / (DIN_ / 256);
    const int ch = blockIdx.x;
    const int c  = ct * 256 + threadIdx.x;
    const float Ac = __ldg(&Aw[c]);
    const int bl0 = b * L_ + ch * CHUNK_;
    size_t base = (size_t)bl0 * DIN_ + c;
    float sum = 0.f;
#pragma unroll 4
    for (int i = 0; i < CHUNK_; i++) {
        size_t off = base + (size_t)i * DIN_;
        float dt = g_dt[off];
        float xc = deq_f(g_xcq0[off], g_xcq1[off], g_sxc[bl0 + i]);
        sum += xc * dt * expf(Ac * dt);
    }
    g_csum[((size_t)b * NCHUNK_ + ch) * DIN_ + c] = sum;
}

// ---------------- scan phase 2: exclusive prefix over chunks --------------
__global__ void __launch_bounds__(256)
scan_phase2()
{
    int idx = blockIdx.x * blockDim.x + threadIdx.x;  // over B_*DIN_
    int c = idx % DIN_;
    int b = idx / DIN_;
    float run = 0.f;
    for (int ch = 0; ch < NCHUNK_; ch++) {
        size_t o = ((size_t)b * NCHUNK_ + ch) * DIN_ + c;
        float v = g_csum[o];
        g_cpre[o] = run;
        run += v;
    }
}

// ---------------- scan phase 3: gate, write fp32 y ------------------------
__global__ void __launch_bounds__(256)
scan_phase3(const float* __restrict__ Aw, const float* __restrict__ Dp)
{
    const int ct = blockIdx.y % (DIN_ / 256);
    const int b  = blockIdx.y / (DIN_ / 256);
    const int ch = blockIdx.x;
    const int c  = ct * 256 + threadIdx.x;
    const float Ac = __ldg(&Aw[c]);
    const float Dc = __ldg(&Dp[c]);
    float run = g_cpre[((size_t)b * NCHUNK_ + ch) * DIN_ + c];
    const int bl0 = b * L_ + ch * CHUNK_;
    size_t base  = (size_t)bl0 * DIN_ + c;
    size_t zbase = (size_t)bl0 * (2 * DIN_) + DIN_ + c;
#pragma unroll 4
    for (int i = 0; i < CHUNK_; i++) {
        size_t off = base + (size_t)i * DIN_;
        float dt = g_dt[off];
        float xc = deq_f(g_xcq0[off], g_xcq1[off], g_sxc[bl0 + i]);
        float ae = expf(Ac * dt);   // bit-identical to phase 1's value
        run += xc * dt * ae;
        float y  = run * ae + xc * Dc;
        float z  = g_xz[zbase + (size_t)i * (2 * DIN_)];
        g_yf[off] = y * silu_f(z);
    }
}

// ---------------------------------------------------------------------------
extern "C" void kernel_launch(void* const* d_in, const int* in_sizes, int n_in,
                              void* d_out, int out_size)
{
    const float* x      = (const float*)d_in[0];
    const float* W_in   = (const float*)d_in[1];
    const float* W_out  = (const float*)d_in[2];
    const float* conv_w = (const float*)d_in[3];
    const float* conv_b = (const float*)d_in[4];
    const float* dt_w   = (const float*)d_in[5];
    const float* dt_b   = (const float*)d_in[6];
    const float* Aw     = (const float*)d_in[7];
    const float* Dp     = (const float*)d_in[8];
    float* out = (float*)d_out;

    float *p_xz, *p_dt, *p_yf;
    int8_t *p_xq0, *p_xq1, *p_wiq0, *p_wiq1, *p_dwq0, *p_dwq1, *p_woq0, *p_woq1;
    int8_t *p_xcq0, *p_xcq1, *p_yq0, *p_yq1;
    float *p_sx, *p_swi, *p_sdw, *p_swo, *p_sxc, *p_sy;
    cudaGetSymbolAddress((void**)&p_xz, g_xz);
    cudaGetSymbolAddress((void**)&p_dt, g_dt);
    cudaGetSymbolAddress((void**)&p_yf, g_yf);
    cudaGetSymbolAddress((void**)&p_xq0, g_xq0);
    cudaGetSymbolAddress((void**)&p_xq1, g_xq1);
    cudaGetSymbolAddress((void**)&p_wiq0, g_wiq0);
    cudaGetSymbolAddress((void**)&p_wiq1, g_wiq1);
    cudaGetSymbolAddress((void**)&p_dwq0, g_dwq0);
    cudaGetSymbolAddress((void**)&p_dwq1, g_dwq1);
    cudaGetSymbolAddress((void**)&p_woq0, g_woq0);
    cudaGetSymbolAddress((void**)&p_woq1, g_woq1);
    cudaGetSymbolAddress((void**)&p_xcq0, g_xcq0);
    cudaGetSymbolAddress((void**)&p_xcq1, g_xcq1);
    cudaGetSymbolAddress((void**)&p_yq0, g_yq0);
    cudaGetSymbolAddress((void**)&p_yq1, g_yq1);
    cudaGetSymbolAddress((void**)&p_sx, g_sx);
    cudaGetSymbolAddress((void**)&p_swi, g_swi);
    cudaGetSymbolAddress((void**)&p_sdw, g_sdw);
    cudaGetSymbolAddress((void**)&p_swo, g_swo);
    cudaGetSymbolAddress((void**)&p_sxc, g_sxc);
    cudaGetSymbolAddress((void**)&p_sy, g_sy);

    cudaFuncSetAttribute(s8_gemm<0>, cudaFuncAttributeMaxDynamicSharedMemorySize, GEMM8_SMEM);
    cudaFuncSetAttribute(s8_gemm<1>, cudaFuncAttributeMaxDynamicSharedMemorySize, GEMM8_SMEM);

    // 1) quantize inputs / weights (per-row, 2 limbs)
    quant_rows<4><<<M_, 256>>>(x, p_xq0, p_xq1, p_sx);              // K=1024
    quant_rows<4><<<2 * DIN_, 256>>>(W_in, p_wiq0, p_wiq1, p_swi);  // K=1024
    quant_rows<6><<<DIN_, 256>>>(dt_w, p_dwq0, p_dwq1, p_sdw);      // K=1536
    quant_rows<6><<<DIM_, 256>>>(W_out, p_woq0, p_woq1, p_swo);     // K=1536

    // 2) in_proj: xz[M,3072] = x @ W_in^T   (int8 IMMA)
    s8_gemm<0><<<dim3((2 * DIN_) / 64, M_ / 128), 256, GEMM8_SMEM>>>(
        p_xq0, p_xq1, p_sx, p_wiq0, p_wiq1, p_swi, p_xz, nullptr, M_, 2 * DIN_, DIM_);

    // 3) depthwise conv3 + bias + SiLU + quantize x_conv
    conv_silu_quant<<<M_, 256>>>(conv_w, conv_b);

    // 4) dt = softplus(x_conv @ dt_w^T + dt_b)
    s8_gemm<1><<<dim3(DIN_ / 64, M_ / 128), 256, GEMM8_SMEM>>>(
        p_xcq0, p_xcq1, p_sxc, p_dwq0, p_dwq1, p_sdw, p_dt, dt_b, M_, DIN_, DIN_);

    // 5) chunked cumsum scan + gating (y fp32)
    scan_phase1<<<dim3(NCHUNK_, B_ * (DIN_ / 256)), 256>>>(Aw);
    scan_phase2<<<(B_ * DIN_) / 256, 256>>>();
    scan_phase3<<<dim3(NCHUNK_, B_ * (DIN_ / 256)), 256>>>(Aw, Dp);

    // 6) quantize y
    quant_rows<6><<<M_, 256>>>(p_yf, p_yq0, p_yq1, p_sy);           // K=1536

    // 7) out_proj: out[M,1024] = y @ W_out^T
    s8_gemm<0><<<dim3(DIM_ / 64, M_ / 128), 256, GEMM8_SMEM>>>(
        p_yq0, p_yq1, p_sy, p_woq0, p_woq1, p_swo, out, nullptr, M_, DIM_, DIN_);
}

// round 15
// speedup vs baseline: 2.5243x; 2.5243x over previous
#include <cuda_runtime.h>
#include <cuda_bf16.h>
#include <math.h>
#include <stdint.h>

#define DIM_  1024
#define DIN_  1536
#define B_    4
#define L_    4096
#define M_    (B_ * L_)          // 16384
#define NCHUNK_ 32
#define CHUNK_  (L_ / NCHUNK_)   // 128

typedef __nv_bfloat16 bf16;

// ---------------- static scratch (no allocations allowed) ----------------
__device__ __align__(16) float g_xz[(size_t)M_ * 2 * DIN_];   // in_proj out [M,3072]
__device__ __align__(16) bf16  g_xch[(size_t)M_ * DIN_];      // silu(conv) hi
__device__ __align__(16) bf16  g_xcl[(size_t)M_ * DIN_];      // silu(conv) lo
__device__ __align__(16) float g_dt[(size_t)M_ * DIN_];
__device__ __align__(16) bf16  g_yh[(size_t)M_ * DIN_];
__device__ __align__(16) bf16  g_yl[(size_t)M_ * DIN_];
__device__ __align__(16) bf16  g_xh[(size_t)M_ * DIM_];
__device__ __align__(16) bf16  g_xl[(size_t)M_ * DIM_];
__device__ __align__(16) bf16  g_wih[(size_t)2 * DIN_ * DIM_];
__device__ __align__(16) bf16  g_wil[(size_t)2 * DIN_ * DIM_];
__device__ __align__(16) bf16  g_dwh[(size_t)DIN_ * DIN_];
__device__ __align__(16) bf16  g_dwl[(size_t)DIN_ * DIN_];
__device__ __align__(16) bf16  g_woh[(size_t)DIM_ * DIN_];
__device__ __align__(16) bf16  g_wol[(size_t)DIM_ * DIN_];
__device__ float g_csum[B_ * NCHUNK_ * DIN_];
__device__ float g_cpre[B_ * NCHUNK_ * DIN_];

__device__ __forceinline__ float softplus_f(float v) {
    return v > 20.f ? v : log1pf(expf(v));
}
__device__ __forceinline__ float silu_f(float v) {
    return v / (1.f + expf(-v));
}
__device__ __forceinline__ void split_bf16(float v, bf16& h, bf16& l) {
    h = __float2bfloat16_rn(v);
    l = __float2bfloat16_rn(v - __bfloat162float(h));
}

// ======================= PTX helpers (base sm_90+/sm_103, no 'a' features) ===
__device__ __forceinline__ uint32_t smem_u32(const void* p) {
    uint32_t a;
    asm("{ .reg .u64 t; cvta.to.shared.u64 t, %1; cvt.u32.u64 %0, t; }" : "=r"(a) : "l"(p));
    return a;
}
#define CP16(saddr, gptr) \
    asm volatile("cp.async.cg.shared.global [%0], [%1], 16;" :: "r"(saddr), "l"(gptr))

#define MBAR_INIT(addr, cnt) \
    asm volatile("mbarrier.init.shared.b64 [%0], %1;" :: "r"(addr), "r"(cnt) : "memory")
#define MBAR_ARRIVE(addr) \
    asm volatile("mbarrier.arrive.shared.b64 _, [%0];" :: "r"(addr) : "memory")
// arrive on mbar when all of this thread's prior cp.asyncs have completed
#define CPA_ARRIVE(addr) \
    asm volatile("cp.async.mbarrier.arrive.noinc.shared.b64 [%0];" :: "r"(addr) : "memory")
#define MBAR_WAIT(addr, ph) do {                                                   \
    uint32_t _m = (addr); uint32_t _p = (ph); uint32_t _d;                         \
    asm volatile("{ .reg .pred p; mbarrier.try_wait.parity.acquire.cta.shared::cta.b64 p, [%1], %2; selp.b32 %0,1,0,p; }" \
        : "=r"(_d) : "r"(_m), "r"(_p) : "memory");                                 \
    if (!_d) {                                                                     \
        asm volatile("{ .reg .pred P1; WL%=: mbarrier.try_wait.parity.acquire.cta.shared::cta.b64 P1, [%0], %1, 0x989680; @P1 bra.uni WD%=; bra.uni WL%=; WD%=: }" \
            :: "r"(_m), "r"(_p) : "memory");                                       \
    } } while (0)

#define LDSM4(r, a) \
    asm volatile("ldmatrix.sync.aligned.m8n8.x4.shared.b16 {%0,%1,%2,%3}, [%4];" \
        : "=r"((r)[0]), "=r"((r)[1]), "=r"((r)[2]), "=r"((r)[3]) : "r"(a))

#define MMA_BF16(d, a, b0v, b1v) \
    asm volatile("mma.sync.aligned.m16n8k16.row.col.f32.bf16.bf16.f32 " \
        "{%0,%1,%2,%3}, {%4,%5,%6,%7}, {%8,%9}, {%0,%1,%2,%3};" \
        : "+f"((d)[0]), "+f"((d)[1]), "+f"((d)[2]), "+f"((d)[3]) \
        : "r"((a)[0]), "r"((a)[1]), "r"((a)[2]), "r"((a)[3]), "r"(b0v), "r"(b1v))

__device__ __forceinline__ uint32_t sw64(uint32_t off) {
    return off ^ ((off >> 3) & 0x30);
}

// ======================= 3x-bf16 mma.sync GEMM, mbarrier pipeline ============
// C[m,n] = sum_k (Ah+Al)[m,k] * (Bh+Bl)[n,k], both K-contiguous bf16.
// Block 128x128, BK=32, 256 threads (8 warps: 2 M x 4 N, warp tile 64x32).
// 3-stage ring, per-stage full/empty mbarriers, NO __syncthreads in the main
// loop. Loads issued 3 chunks ahead (~2 chunks of MMA cover cp.async latency).
#define BK_      32
#define STAGES_  3
#define STAGE_B  32768          // Ah 8K | Al 8K | Bh 8K | Bl 8K
#define AH_OFF   0
#define AL_OFF   8192
#define BH_OFF   16384
#define BL_OFF   24576
#define GEMM_SMEM (STAGES_ * STAGE_B)   // 96 KB

__device__ __forceinline__ void load_stage(
    uint32_t sb, const bf16* __restrict__ Ah, const bf16* __restrict__ Al,
    const bf16* __restrict__ Bh, const bf16* __restrict__ Bl,
    int row0, int col0, int k0, int K, int tid)
{
#pragma unroll
    for (int i = 0; i < 2; ++i) {
        const int idx = tid + i * 256;          // 0..511
        const int r  = idx >> 2;                // 0..127
        const int kg = idx & 3;                 // 16B group along K
        const uint32_t so = sw64((uint32_t)(r * 64 + kg * 16));
        const size_t ga = (size_t)(row0 + r) * K + k0 + kg * 8;
        const size_t gb = (size_t)(col0 + r) * K + k0 + kg * 8;
        CP16(sb + AH_OFF + so, Ah + ga);
        CP16(sb + AL_OFF + so, Al + ga);
        CP16(sb + BH_OFF + so, Bh + gb);
        CP16(sb + BL_OFF + so, Bl + gb);
    }
}

// MODE 0: plain store.  MODE 1: softplus(acc + bias[n]).
template <int MODE>
__global__ void __launch_bounds__(256, 2)
bf16_gemm(const bf16* __restrict__ Ah, const bf16* __restrict__ Al,
          const bf16* __restrict__ Bh, const bf16* __restrict__ Bl,
          float* __restrict__ C, const float* __restrict__ bias,
          int M, int N, int K)
{
    extern __shared__ char smem_raw[];
    __shared__ __align__(8) uint64_t s_mbar[2 * STAGES_];  // full[3], empty[3]
    const uint32_t smb = smem_u32(smem_raw);
    const int tid  = threadIdx.x;
    const int lane = tid & 31;
    const int wid  = tid >> 5;
    const int wm   = (wid >> 2) * 64;   // warp M base within block
    const int wn   = (wid & 3) * 32;    // warp N base within block
    const int row0 = blockIdx.y * 128;
    const int col0 = blockIdx.x * 128;
    const int nch  = K / BK_;

    if (tid == 0) {
#pragma unroll
        for (int s = 0; s < 2 * STAGES_; ++s)
            MBAR_INIT(smem_u32(&s_mbar[s]), 256);
    }
    __syncthreads();

    float acc[4][4][4];
#pragma unroll
    for (int i = 0; i < 4; ++i)
#pragma unroll
        for (int j = 0; j < 4; ++j)
#pragma unroll
            for (int t = 0; t < 4; ++t) acc[i][j][t] = 0.f;

    // prologue: fill all 3 stages (stages start empty, no wait needed)
#pragma unroll
    for (int h = 0; h < STAGES_; ++h) {
        load_stage(smb + h * STAGE_B, Ah, Al, Bh, Bl, row0, col0, h * BK_, K, tid);
        CPA_ARRIVE(smem_u32(&s_mbar[h]));
    }

    // hoisted per-lane ldmatrix tile-local swizzled offsets
    const int a_row = (lane & 7) + ((lane >> 3) & 1) * 8;
    const int a_kof = ((lane >> 4) & 1) * 16;
    const int b_row = (lane & 7) + ((lane >> 4) & 1) * 8;
    const int b_kof = ((lane >> 3) & 1) * 16;
    uint32_t offA[2][4], offB[2][2];
#pragma unroll
    for (int ks = 0; ks < 2; ++ks) {
#pragma unroll
        for (int mt = 0; mt < 4; ++mt)
            offA[ks][mt] = AH_OFF +
                sw64((uint32_t)((wm + mt * 16 + a_row) * 64 + ks * 32 + a_kof));
#pragma unroll
        for (int np = 0; np < 2; ++np)
            offB[ks][np] = BH_OFF +
                sw64((uint32_t)((wn + np * 16 + b_row) * 64 + ks * 32 + b_kof));
    }

    int s = 0;           // stage cursor
    uint32_t par = 0;    // parity (flips when s wraps)
    for (int c = 0; c < nch; ++c) {
        const uint32_t sb  = smb + s * STAGE_B;
        const uint32_t mbf = smem_u32(&s_mbar[s]);
        const uint32_t mbe = smem_u32(&s_mbar[STAGES_ + s]);

        MBAR_WAIT(mbf, par);   // all threads' copies for this stage landed
#pragma unroll
        for (int ks = 0; ks < 2; ++ks) {
            uint32_t fBh[2][4], fBl[2][4];
#pragma unroll
            for (int np = 0; np < 2; ++np) {
                LDSM4(fBh[np], sb + offB[ks][np]);
                LDSM4(fBl[np], sb + offB[ks][np] + (BL_OFF - BH_OFF));
            }
#pragma unroll
            for (int mt = 0; mt < 4; ++mt) {
                uint32_t fAh[4], fAl[4];
                LDSM4(fAh, sb + offA[ks][mt]);
                LDSM4(fAl, sb + offA[ks][mt] + (AL_OFF - AH_OFF));
                // last LDSM of this stage -> signal "stage read complete"
                if (ks == 1 && mt == 3) MBAR_ARRIVE(mbe);
#pragma unroll
                for (int nt = 0; nt < 4; ++nt) {
                    const int np = nt >> 1, rr = (nt & 1) * 2;
                    MMA_BF16(acc[mt][nt], fAh, fBh[np][rr], fBh[np][rr + 1]);
                }
#pragma unroll
                for (int nt = 0; nt < 4; ++nt) {
                    const int np = nt >> 1, rr = (nt & 1) * 2;
                    MMA_BF16(acc[mt][nt], fAh, fBl[np][rr], fBl[np][rr + 1]);
                }
#pragma unroll
                for (int nt = 0; nt < 4; ++nt) {
                    const int np = nt >> 1, rr = (nt & 1) * 2;
                    MMA_BF16(acc[mt][nt], fAl, fBh[np][rr], fBh[np][rr + 1]);
                }
            }
        }
        if (c + STAGES_ < nch) {
            // overwrite guard: waits only for all warps' LDSM of THIS chunk
            MBAR_WAIT(mbe, par);
            load_stage(sb, Ah, Al, Bh, Bl, row0, col0, (c + STAGES_) * BK_, K, tid);
            CPA_ARRIVE(mbf);
        }
        if (++s == STAGES_) { s = 0; par ^= 1; }
    }

    // epilogue: direct float2 stores
#pragma unroll
    for (int mt = 0; mt < 4; ++mt) {
        const int r0 = row0 + wm + mt * 16 + (lane >> 2);
#pragma unroll
        for (int nt = 0; nt < 4; ++nt) {
            const int cc = col0 + wn + nt * 8 + (lane & 3) * 2;
            float v0 = acc[mt][nt][0], v1 = acc[mt][nt][1];
            float v2 = acc[mt][nt][2], v3 = acc[mt][nt][3];
            if (MODE == 1) {
                const float b0 = __ldg(&bias[cc]), b1 = __ldg(&bias[cc + 1]);
                v0 = softplus_f(v0 + b0); v1 = softplus_f(v1 + b1);
                v2 = softplus_f(v2 + b0); v3 = softplus_f(v3 + b1);
            }
            *(float2*)&C[(size_t)r0 * N + cc]       = make_float2(v0, v1);
            *(float2*)&C[(size_t)(r0 + 8) * N + cc] = make_float2(v2, v3);
        }
    }
}

// ---------------- fused hi/lo bf16 split of all four fp32 sources ----------
#define N0_ (M_ * DIM_)            // x
#define N1_ (2 * DIN_ * DIM_)      // W_in
#define N2_ (DIN_ * DIN_)          // dt_w
#define N3_ (DIM_ * DIN_)          // W_out
#define NSPLIT4_ ((N0_ + N1_ + N2_ + N3_) / 4)

__device__ __forceinline__ void split4_store(const float4 v, bf16* hi, bf16* lo, int i4)
{
    bf16 h0, l0, h1, l1, h2, l2, h3, l3;
    split_bf16(v.x, h0, l0); split_bf16(v.y, h1, l1);
    split_bf16(v.z, h2, l2); split_bf16(v.w, h3, l3);
    ushort4 hv = make_ushort4(__bfloat16_as_ushort(h0), __bfloat16_as_ushort(h1),
                              __bfloat16_as_ushort(h2), __bfloat16_as_ushort(h3));
    ushort4 lv = make_ushort4(__bfloat16_as_ushort(l0), __bfloat16_as_ushort(l1),
                              __bfloat16_as_ushort(l2), __bfloat16_as_ushort(l3));
    *(ushort4*)&hi[i4 * 4] = hv;
    *(ushort4*)&lo[i4 * 4] = lv;
}

__global__ void __launch_bounds__(256)
split_all_kernel(const float* __restrict__ x, const float* __restrict__ W_in,
                 const float* __restrict__ dt_w, const float* __restrict__ W_out)
{
    int i = blockIdx.x * blockDim.x + threadIdx.x;
    if (i >= NSPLIT4_) return;
    if (i < N0_ / 4) {
        split4_store(*(const float4*)&x[i * 4], g_xh, g_xl, i);
    } else if (i < (N0_ + N1_) / 4) {
        int j = i - N0_ / 4;
        split4_store(*(const float4*)&W_in[j * 4], g_wih, g_wil, j);
    } else if (i < (N0_ + N1_ + N2_) / 4) {
        int j = i - (N0_ + N1_) / 4;
        split4_store(*(const float4*)&dt_w[j * 4], g_dwh, g_dwl, j);
    } else {
        int j = i - (N0_ + N1_ + N2_) / 4;
        split4_store(*(const float4*)&W_out[j * 4], g_woh, g_wol, j);
    }
}

// ---------------- depthwise conv3 (pad=1) + bias + SiLU + split -----------
__global__ void __launch_bounds__(256)
conv_silu_kernel(const float* __restrict__ cw, const float* __restrict__ cb)
{
    int idx = blockIdx.x * blockDim.x + threadIdx.x;  // over M_*DIN_
    int c  = idx % DIN_;
    int bl = idx / DIN_;
    int l  = bl % L_;
    const float* base = g_xz + (size_t)bl * (2 * DIN_) + c;
    float x0 = base[0];
    float xm = (l > 0)      ? base[-(2 * DIN_)] : 0.f;
    float xp = (l < L_ - 1) ? base[ (2 * DIN_)] : 0.f;
    float w0 = __ldg(&cw[c * 3 + 0]);
    float w1 = __ldg(&cw[c * 3 + 1]);
    float w2 = __ldg(&cw[c * 3 + 2]);
    float v = fmaf(w0, xm, fmaf(w1, x0, fmaf(w2, xp, __ldg(&cb[c]))));
    v = silu_f(v);
    bf16 h, lo;
    split_bf16(v, h, lo);
    g_xch[idx] = h;
    g_xcl[idx] = lo;
}

// ---------------- scan phase 1: per-chunk sums only (ae/s recomputed) -----
__global__ void __launch_bounds__(256)
scan_phase1(const float* __restrict__ Aw)
{
    const int ct = blockIdx.y % (DIN_ / 256);
    const int b  = blockIdx.y / (DIN_ / 256);
    const int ch = blockIdx.x;
    const int c  = ct * 256 + threadIdx.x;
    const float Ac = __ldg(&Aw[c]);
    size_t base = ((size_t)b * L_ + (size_t)ch * CHUNK_) * DIN_ + c;
    float sum = 0.f;
#pragma unroll 4
    for (int i = 0; i < CHUNK_; i++) {
        size_t off = base + (size_t)i * DIN_;
        float dt = g_dt[off];
        float xc = __bfloat162float(g_xch[off]) + __bfloat162float(g_xcl[off]);
        sum += xc * dt * expf(Ac * dt);
    }
    g_csum[((size_t)b * NCHUNK_ + ch) * DIN_ + c] = sum;
}

// ---------------- scan phase 2: exclusive prefix over chunks --------------
__global__ void __launch_bounds__(256)
scan_phase2()
{
    int idx = blockIdx.x * blockDim.x + threadIdx.x;  // over B_*DIN_
    int c = idx % DIN_;
    int b = idx / DIN_;
    float run = 0.f;
    for (int ch = 0; ch < NCHUNK_; ch++) {
        size_t o = ((size_t)b * NCHUNK_ + ch) * DIN_ + c;
        float v = g_csum[o];
        g_cpre[o] = run;
        run += v;
    }
}

// ---------------- scan phase 3: recompute ae/s, gate, split ---------------
__global__ void __launch_bounds__(256)
scan_phase3(const float* __restrict__ Aw, const float* __restrict__ Dp)
{
    const int ct = blockIdx.y % (DIN_ / 256);
    const int b  = blockIdx.y / (DIN_ / 256);
    const int ch = blockIdx.x;
    const int c  = ct * 256 + threadIdx.x;
    const float Ac = __ldg(&Aw[c]);
    const float Dc = __ldg(&Dp[c]);
    float run = g_cpre[((size_t)b * NCHUNK_ + ch) * DIN_ + c];
    size_t base  = ((size_t)b * L_ + (size_t)ch * CHUNK_) * DIN_ + c;
    size_t zbase = ((size_t)b * L_ + (size_t)ch * CHUNK_) * (2 * DIN_) + DIN_ + c;
#pragma unroll 4
    for (int i = 0; i < CHUNK_; i++) {
        size_t off = base + (size_t)i * DIN_;
        float dt = g_dt[off];
        float xc = __bfloat162float(g_xch[off]) + __bfloat162float(g_xcl[off]);
        float ae = expf(Ac * dt);   // bit-identical to phase 1's value
        run += xc * dt * ae;
        float y  = run * ae + xc * Dc;
        float z  = g_xz[zbase + (size_t)i * (2 * DIN_)];
        y *= silu_f(z);
        bf16 h, lo;
        split_bf16(y, h, lo);
        g_yh[off] = h;
        g_yl[off] = lo;
    }
}

// ---------------------------------------------------------------------------
extern "C" void kernel_launch(void* const* d_in, const int* in_sizes, int n_in,
                              void* d_out, int out_size)
{
    const float* x      = (const float*)d_in[0];
    const float* W_in   = (const float*)d_in[1];
    const float* W_out  = (const float*)d_in[2];
    const float* conv_w = (const float*)d_in[3];
    const float* conv_b = (const float*)d_in[4];
    const float* dt_w   = (const float*)d_in[5];
    const float* dt_b   = (const float*)d_in[6];
    const float* Aw     = (const float*)d_in[7];
    const float* Dp     = (const float*)d_in[8];
    float* out = (float*)d_out;

    float *p_xz, *p_dt;
    bf16 *p_xh, *p_xl, *p_wih, *p_wil, *p_dwh, *p_dwl, *p_woh, *p_wol;
    bf16 *p_xch, *p_xcl, *p_yh, *p_yl;
    cudaGetSymbolAddress((void**)&p_xz, g_xz);
    cudaGetSymbolAddress((void**)&p_dt, g_dt);
    cudaGetSymbolAddress((void**)&p_xh, g_xh);
    cudaGetSymbolAddress((void**)&p_xl, g_xl);
    cudaGetSymbolAddress((void**)&p_wih, g_wih);
    cudaGetSymbolAddress((void**)&p_wil, g_wil);
    cudaGetSymbolAddress((void**)&p_dwh, g_dwh);
    cudaGetSymbolAddress((void**)&p_dwl, g_dwl);
    cudaGetSymbolAddress((void**)&p_woh, g_woh);
    cudaGetSymbolAddress((void**)&p_wol, g_wol);
    cudaGetSymbolAddress((void**)&p_xch, g_xch);
    cudaGetSymbolAddress((void**)&p_xcl, g_xcl);
    cudaGetSymbolAddress((void**)&p_yh, g_yh);
    cudaGetSymbolAddress((void**)&p_yl, g_yl);

    cudaFuncSetAttribute(bf16_gemm<0>, cudaFuncAttributeMaxDynamicSharedMemorySize, GEMM_SMEM);
    cudaFuncSetAttribute(bf16_gemm<1>, cudaFuncAttributeMaxDynamicSharedMemorySize, GEMM_SMEM);

    // 1) fused bf16 hi/lo splits (x, W_in, dt_w, W_out)
    split_all_kernel<<<(NSPLIT4_ + 255) / 256, 256>>>(x, W_in, dt_w, W_out);

    // 2) in_proj: xz[M,3072] = x @ W_in^T   (3x-bf16 mma)
    bf16_gemm<0><<<dim3((2 * DIN_) / 128, M_ / 128), 256, GEMM_SMEM>>>(
        p_xh, p_xl, p_wih, p_wil, p_xz, nullptr, M_, 2 * DIN_, DIM_);

    // 3) depthwise conv3 + bias + SiLU (+ split)
    conv_silu_kernel<<<(M_ * DIN_) / 256, 256>>>(conv_w, conv_b);

    // 4) dt = softplus(x_conv @ dt_w^T + dt_b)  <- launch slot 4: ncu target
    bf16_gemm<1><<<dim3(DIN_ / 128, M_ / 128), 256, GEMM_SMEM>>>(
        p_xch, p_xcl, p_dwh, p_dwl, p_dt, dt_b, M_, DIN_, DIN_);

    // 5) chunked cumsum scan + gating (y written as bf16 hi/lo)
    scan_phase1<<<dim3(NCHUNK_, B_ * (DIN_ / 256)), 256>>>(Aw);
    scan_phase2<<<(B_ * DIN_) / 256, 256>>>();
    scan_phase3<<<dim3(NCHUNK_, B_ * (DIN_ / 256)), 256>>>(Aw, Dp);

    // 6) out_proj: out[M,1024] = y @ W_out^T
    bf16_gemm<0><<<dim3(DIM_ / 128, M_ / 128), 256, GEMM_SMEM>>>(
        p_yh, p_yl, p_woh, p_wol, out, nullptr, M_, DIM_, DIN_);
}

// round 16
// speedup vs baseline: 3.8096x; 1.5092x over previous
#include <cuda_runtime.h>
#include <cuda_fp16.h>
#include <math.h>
#include <stdint.h>

#define DIM_  1024
#define DIN_  1536
#define B_    4
#define L_    4096
#define M_    (B_ * L_)          // 16384
#define NCHUNK_ 32
#define CHUNK_  (L_ / NCHUNK_)   // 128

typedef __half fp16;

// ---------------- static scratch (no allocations allowed) ----------------
__device__ __align__(16) float g_xz[(size_t)M_ * 2 * DIN_];   // in_proj out [M,3072]
__device__ __align__(16) fp16  g_xch[(size_t)M_ * DIN_];      // silu(conv) hi limb
__device__ __align__(16) fp16  g_xcl[(size_t)M_ * DIN_];      // silu(conv) lo limb
__device__ __align__(16) float g_dt[(size_t)M_ * DIN_];
__device__ __align__(16) fp16  g_yh[(size_t)M_ * DIN_];
__device__ __align__(16) fp16  g_yl[(size_t)M_ * DIN_];
__device__ __align__(16) fp16  g_xh[(size_t)M_ * DIM_];
__device__ __align__(16) fp16  g_xl[(size_t)M_ * DIM_];
__device__ __align__(16) fp16  g_wi[(size_t)2 * DIN_ * DIM_]; // weights: single fp16 limb
__device__ __align__(16) fp16  g_dw[(size_t)DIN_ * DIN_];
__device__ __align__(16) fp16  g_wo[(size_t)DIM_ * DIN_];
__device__ float g_csum[B_ * NCHUNK_ * DIN_];
__device__ float g_cpre[B_ * NCHUNK_ * DIN_];

__device__ __forceinline__ float softplus_f(float v) {
    return v > 20.f ? v : log1pf(expf(v));
}
__device__ __forceinline__ float silu_f(float v) {
    return v / (1.f + expf(-v));
}
__device__ __forceinline__ void split_fp16(float v, fp16& h, fp16& l) {
    h = __float2half_rn(v);
    l = __float2half_rn(v - __half2float(h));
}

// ======================= PTX helpers (base sm_90+/sm_103, no 'a' features) ===
__device__ __forceinline__ uint32_t smem_u32(const void* p) {
    uint32_t a;
    asm("{ .reg .u64 t; cvta.to.shared.u64 t, %1; cvt.u32.u64 %0, t; }" : "=r"(a) : "l"(p));
    return a;
}
#define CP16(saddr, gptr) \
    asm volatile("cp.async.cg.shared.global [%0], [%1], 16;" :: "r"(saddr), "l"(gptr))

#define MBAR_INIT(addr, cnt) \
    asm volatile("mbarrier.init.shared.b64 [%0], %1;" :: "r"(addr), "r"(cnt) : "memory")
#define MBAR_ARRIVE(addr) \
    asm volatile("mbarrier.arrive.shared.b64 _, [%0];" :: "r"(addr) : "memory")
// arrive on mbar when all of this thread's prior cp.asyncs have completed
#define CPA_ARRIVE(addr) \
    asm volatile("cp.async.mbarrier.arrive.noinc.shared.b64 [%0];" :: "r"(addr) : "memory")
#define MBAR_WAIT(addr, ph) do {                                                   \
    uint32_t _m = (addr); uint32_t _p = (ph); uint32_t _d;                         \
    asm volatile("{ .reg .pred p; mbarrier.try_wait.parity.acquire.cta.shared::cta.b64 p, [%1], %2; selp.b32 %0,1,0,p; }" \
        : "=r"(_d) : "r"(_m), "r"(_p) : "memory");                                 \
    if (!_d) {                                                                     \
        asm volatile("{ .reg .pred P1; WL%=: mbarrier.try_wait.parity.acquire.cta.shared::cta.b64 P1, [%0], %1, 0x989680; @P1 bra.uni WD%=; bra.uni WL%=; WD%=: }" \
            :: "r"(_m), "r"(_p) : "memory");                                       \
    } } while (0)

#define LDSM4(r, a) \
    asm volatile("ldmatrix.sync.aligned.m8n8.x4.shared.b16 {%0,%1,%2,%3}, [%4];" \
        : "=r"((r)[0]), "=r"((r)[1]), "=r"((r)[2]), "=r"((r)[3]) : "r"(a))

#define MMA_F16(d, a, b0v, b1v) \
    asm volatile("mma.sync.aligned.m16n8k16.row.col.f32.f16.f16.f32 " \
        "{%0,%1,%2,%3}, {%4,%5,%6,%7}, {%8,%9}, {%0,%1,%2,%3};" \
        : "+f"((d)[0]), "+f"((d)[1]), "+f"((d)[2]), "+f"((d)[3]) \
        : "r"((a)[0]), "r"((a)[1]), "r"((a)[2]), "r"((a)[3]), "r"(b0v), "r"(b1v))

__device__ __forceinline__ uint32_t sw64(uint32_t off) {
    return off ^ ((off >> 3) & 0x30);
}

// ============== 2-product fp16 mma.sync GEMM, 2-stage mbarrier pipeline ======
// C[m,n] = sum_k (Ah+Al)[m,k] * B[n,k]; Ah/Al fp16 limbs of A, B single fp16.
// Block 128x128, BK=32, 256 threads (8 warps: 2 M x 4 N, warp tile 64x32).
// 2-stage ping-pong (fully unrolled stage addressing — R13's proven scheduler).
#define BK_      32
#define STAGE_B  24576          // Ah 8K | Al 8K | B 8K
#define AH_OFF   0
#define AL_OFF   8192
#define B_OFF    16384
#define GEMM_SMEM (2 * STAGE_B)   // 48 KB

__device__ __forceinline__ void load_stage(
    uint32_t sb, const fp16* __restrict__ Ah, const fp16* __restrict__ Al,
    const fp16* __restrict__ Bw,
    int row0, int col0, int k0, int K, int tid)
{
#pragma unroll
    for (int i = 0; i < 2; ++i) {
        const int idx = tid + i * 256;          // 0..511
        const int r  = idx >> 2;                // 0..127
        const int kg = idx & 3;                 // 16B group along K
        const uint32_t so = sw64((uint32_t)(r * 64 + kg * 16));
        const size_t ga = (size_t)(row0 + r) * K + k0 + kg * 8;
        const size_t gb = (size_t)(col0 + r) * K + k0 + kg * 8;
        CP16(sb + AH_OFF + so, Ah + ga);
        CP16(sb + AL_OFF + so, Al + ga);
        CP16(sb + B_OFF  + so, Bw + gb);
    }
}

// MODE 0: plain store.  MODE 1: softplus(acc + bias[n]).
template <int MODE>
__global__ void __launch_bounds__(256, 2)
f16_gemm(const fp16* __restrict__ Ah, const fp16* __restrict__ Al,
         const fp16* __restrict__ Bw,
         float* __restrict__ C, const float* __restrict__ bias,
         int M, int N, int K)
{
    extern __shared__ char smem_raw[];
    __shared__ __align__(8) uint64_t s_mbar[4];   // full0, full1, empty0, empty1
    const uint32_t smb = smem_u32(smem_raw);
    const int tid  = threadIdx.x;
    const int lane = tid & 31;
    const int wid  = tid >> 5;
    const int wm   = (wid >> 2) * 64;   // warp M base within block
    const int wn   = (wid & 3) * 32;    // warp N base within block
    const int row0 = blockIdx.y * 128;
    const int col0 = blockIdx.x * 128;
    const int nch  = K / BK_;           // even for all three GEMMs

    if (tid == 0) {
        MBAR_INIT(smem_u32(&s_mbar[0]), 256);
        MBAR_INIT(smem_u32(&s_mbar[1]), 256);
        MBAR_INIT(smem_u32(&s_mbar[2]), 256);
        MBAR_INIT(smem_u32(&s_mbar[3]), 256);
    }
    __syncthreads();
    const uint32_t mbf0 = smem_u32(&s_mbar[0]);
    const uint32_t mbf1 = smem_u32(&s_mbar[1]);
    const uint32_t mbe0 = smem_u32(&s_mbar[2]);
    const uint32_t mbe1 = smem_u32(&s_mbar[3]);

    float acc[4][4][4];
#pragma unroll
    for (int i = 0; i < 4; ++i)
#pragma unroll
        for (int j = 0; j < 4; ++j)
#pragma unroll
            for (int t = 0; t < 4; ++t) acc[i][j][t] = 0.f;

    // prologue: fill both stages (stages start empty, no wait needed)
    load_stage(smb, Ah, Al, Bw, row0, col0, 0, K, tid);
    CPA_ARRIVE(mbf0);
    load_stage(smb + STAGE_B, Ah, Al, Bw, row0, col0, BK_, K, tid);
    CPA_ARRIVE(mbf1);

    // hoisted per-lane ldmatrix tile-local swizzled offsets
    const int a_row = (lane & 7) + ((lane >> 3) & 1) * 8;
    const int a_kof = ((lane >> 4) & 1) * 16;
    const int b_row = (lane & 7) + ((lane >> 4) & 1) * 8;
    const int b_kof = ((lane >> 3) & 1) * 16;
    uint32_t offA[2][4], offB[2][2];
#pragma unroll
    for (int ks = 0; ks < 2; ++ks) {
#pragma unroll
        for (int mt = 0; mt < 4; ++mt)
            offA[ks][mt] = AH_OFF +
                sw64((uint32_t)((wm + mt * 16 + a_row) * 64 + ks * 32 + a_kof));
#pragma unroll
        for (int np = 0; np < 2; ++np)
            offB[ks][np] = B_OFF +
                sw64((uint32_t)((wn + np * 16 + b_row) * 64 + ks * 32 + b_kof));
    }

    const int T = nch >> 1;
    for (int t = 0; t < T; ++t) {
        const uint32_t par = (uint32_t)(t & 1);
#pragma unroll
        for (int h = 0; h < 2; ++h) {
            const uint32_t sb  = smb + h * STAGE_B;
            const uint32_t mbf = h ? mbf1 : mbf0;
            const uint32_t mbe = h ? mbe1 : mbe0;

            MBAR_WAIT(mbf, par);   // all threads' copies for this stage landed
#pragma unroll
            for (int ks = 0; ks < 2; ++ks) {
                uint32_t fB[2][4];
#pragma unroll
                for (int np = 0; np < 2; ++np)
                    LDSM4(fB[np], sb + offB[ks][np]);
#pragma unroll
                for (int mt = 0; mt < 4; ++mt) {
                    uint32_t fAh[4], fAl[4];
                    LDSM4(fAh, sb + offA[ks][mt]);
                    LDSM4(fAl, sb + offA[ks][mt] + (AL_OFF - AH_OFF));
                    // last LDSM of this stage -> signal "stage read complete"
                    if (ks == 1 && mt == 3) MBAR_ARRIVE(mbe);
                    // product-major: dependent MMAs into same acc 4 apart
#pragma unroll
                    for (int nt = 0; nt < 4; ++nt) {
                        const int np = nt >> 1, rr = (nt & 1) * 2;
                        MMA_F16(acc[mt][nt], fAh, fB[np][rr], fB[np][rr + 1]);
                    }
#pragma unroll
                    for (int nt = 0; nt < 4; ++nt) {
                        const int np = nt >> 1, rr = (nt & 1) * 2;
                        MMA_F16(acc[mt][nt], fAl, fB[np][rr], fB[np][rr + 1]);
                    }
                }
            }
            if (t < T - 1) {
                // overwrite guard: waits only for all warps' LDSM of THIS stage
                MBAR_WAIT(mbe, par);
                load_stage(sb, Ah, Al, Bw, row0, col0,
                           (2 * t + h + 2) * BK_, K, tid);
                CPA_ARRIVE(mbf);
            }
        }
    }

    // epilogue: direct float2 stores
#pragma unroll
    for (int mt = 0; mt < 4; ++mt) {
        const int r0 = row0 + wm + mt * 16 + (lane >> 2);
#pragma unroll
        for (int nt = 0; nt < 4; ++nt) {
            const int cc = col0 + wn + nt * 8 + (lane & 3) * 2;
            float v0 = acc[mt][nt][0], v1 = acc[mt][nt][1];
            float v2 = acc[mt][nt][2], v3 = acc[mt][nt][3];
            if (MODE == 1) {
                const float b0 = __ldg(&bias[cc]), b1 = __ldg(&bias[cc + 1]);
                v0 = softplus_f(v0 + b0); v1 = softplus_f(v1 + b1);
                v2 = softplus_f(v2 + b0); v3 = softplus_f(v3 + b1);
            }
            *(float2*)&C[(size_t)r0 * N + cc]       = make_float2(v0, v1);
            *(float2*)&C[(size_t)(r0 + 8) * N + cc] = make_float2(v2, v3);
        }
    }
}

// ---------------- fused splits: x -> 2 fp16 limbs; weights -> 1 fp16 -------
#define N0_ (M_ * DIM_)            // x (2 limbs)
#define N1_ (2 * DIN_ * DIM_)      // W_in (1 limb)
#define N2_ (DIN_ * DIN_)          // dt_w (1 limb)
#define N3_ (DIM_ * DIN_)          // W_out (1 limb)
#define NSPLIT4_ ((N0_ + N1_ + N2_ + N3_) / 4)

__device__ __forceinline__ void split4_store(const float4 v, fp16* hi, fp16* lo, int i4)
{
    fp16 h0, l0, h1, l1, h2, l2, h3, l3;
    split_fp16(v.x, h0, l0); split_fp16(v.y, h1, l1);
    split_fp16(v.z, h2, l2); split_fp16(v.w, h3, l3);
    ushort4 hv = make_ushort4(__half_as_ushort(h0), __half_as_ushort(h1),
                              __half_as_ushort(h2), __half_as_ushort(h3));
    ushort4 lv = make_ushort4(__half_as_ushort(l0), __half_as_ushort(l1),
                              __half_as_ushort(l2), __half_as_ushort(l3));
    *(ushort4*)&hi[i4 * 4] = hv;
    *(ushort4*)&lo[i4 * 4] = lv;
}

__device__ __forceinline__ void cvt4_store(const float4 v, fp16* dst, int i4)
{
    ushort4 w = make_ushort4(
        __half_as_ushort(__float2half_rn(v.x)), __half_as_ushort(__float2half_rn(v.y)),
        __half_as_ushort(__float2half_rn(v.z)), __half_as_ushort(__float2half_rn(v.w)));
    *(ushort4*)&dst[i4 * 4] = w;
}

__global__ void __launch_bounds__(256)
split_all_kernel(const float* __restrict__ x, const float* __restrict__ W_in,
                 const float* __restrict__ dt_w, const float* __restrict__ W_out)
{
    int i = blockIdx.x * blockDim.x + threadIdx.x;
    if (i >= NSPLIT4_) return;
    if (i < N0_ / 4) {
        split4_store(*(const float4*)&x[i * 4], g_xh, g_xl, i);
    } else if (i < (N0_ + N1_) / 4) {
        int j = i - N0_ / 4;
        cvt4_store(*(const float4*)&W_in[j * 4], g_wi, j);
    } else if (i < (N0_ + N1_ + N2_) / 4) {
        int j = i - (N0_ + N1_) / 4;
        cvt4_store(*(const float4*)&dt_w[j * 4], g_dw, j);
    } else {
        int j = i - (N0_ + N1_ + N2_) / 4;
        cvt4_store(*(const float4*)&W_out[j * 4], g_wo, j);
    }
}

// ---------------- depthwise conv3 (pad=1) + bias + SiLU + split -----------
__global__ void __launch_bounds__(256)
conv_silu_kernel(const float* __restrict__ cw, const float* __restrict__ cb)
{
    int idx = blockIdx.x * blockDim.x + threadIdx.x;  // over M_*DIN_
    int c  = idx % DIN_;
    int bl = idx / DIN_;
    int l  = bl % L_;
    const float* base = g_xz + (size_t)bl * (2 * DIN_) + c;
    float x0 = base[0];
    float xm = (l > 0)      ? base[-(2 * DIN_)] : 0.f;
    float xp = (l < L_ - 1) ? base[ (2 * DIN_)] : 0.f;
    float w0 = __ldg(&cw[c * 3 + 0]);
    float w1 = __ldg(&cw[c * 3 + 1]);
    float w2 = __ldg(&cw[c * 3 + 2]);
    float v = fmaf(w0, xm, fmaf(w1, x0, fmaf(w2, xp, __ldg(&cb[c]))));
    v = silu_f(v);
    fp16 h, lo;
    split_fp16(v, h, lo);
    g_xch[idx] = h;
    g_xcl[idx] = lo;
}

// ---------------- scan phase 1: per-chunk sums only -----------------------
__global__ void __launch_bounds__(256)
scan_phase1(const float* __restrict__ Aw)
{
    const int ct = blockIdx.y % (DIN_ / 256);
    const int b  = blockIdx.y / (DIN_ / 256);
    const int ch = blockIdx.x;
    const int c  = ct * 256 + threadIdx.x;
    const float Ac = __ldg(&Aw[c]);
    size_t base = ((size_t)b * L_ + (size_t)ch * CHUNK_) * DIN_ + c;
    float sum = 0.f;
#pragma unroll 4
    for (int i = 0; i < CHUNK_; i++) {
        size_t off = base + (size_t)i * DIN_;
        float dt = g_dt[off];
        float xc = __half2float(g_xch[off]) + __half2float(g_xcl[off]);
        sum += xc * dt * expf(Ac * dt);
    }
    g_csum[((size_t)b * NCHUNK_ + ch) * DIN_ + c] = sum;
}

// ---------------- scan phase 2: exclusive prefix over chunks --------------
__global__ void __launch_bounds__(256)
scan_phase2()
{
    int idx = blockIdx.x * blockDim.x + threadIdx.x;  // over B_*DIN_
    int c = idx % DIN_;
    int b = idx / DIN_;
    float run = 0.f;
    for (int ch = 0; ch < NCHUNK_; ch++) {
        size_t o = ((size_t)b * NCHUNK_ + ch) * DIN_ + c;
        float v = g_csum[o];
        g_cpre[o] = run;
        run += v;
    }
}

// ---------------- scan phase 3: recompute ae, gate, split -----------------
__global__ void __launch_bounds__(256)
scan_phase3(const float* __restrict__ Aw, const float* __restrict__ Dp)
{
    const int ct = blockIdx.y % (DIN_ / 256);
    const int b  = blockIdx.y / (DIN_ / 256);
    const int ch = blockIdx.x;
    const int c  = ct * 256 + threadIdx.x;
    const float Ac = __ldg(&Aw[c]);
    const float Dc = __ldg(&Dp[c]);
    float run = g_cpre[((size_t)b * NCHUNK_ + ch) * DIN_ + c];
    size_t base  = ((size_t)b * L_ + (size_t)ch * CHUNK_) * DIN_ + c;
    size_t zbase = ((size_t)b * L_ + (size_t)ch * CHUNK_) * (2 * DIN_) + DIN_ + c;
#pragma unroll 4
    for (int i = 0; i < CHUNK_; i++) {
        size_t off = base + (size_t)i * DIN_;
        float dt = g_dt[off];
        float xc = __half2float(g_xch[off]) + __half2float(g_xcl[off]);
        float ae = expf(Ac * dt);   // bit-identical to phase 1's value
        run += xc * dt * ae;
        float y  = run * ae + xc * Dc;
        float z  = g_xz[zbase + (size_t)i * (2 * DIN_)];
        y *= silu_f(z);
        fp16 h, lo;
        split_fp16(y, h, lo);
        g_yh[off] = h;
        g_yl[off] = lo;
    }
}

// ---------------------------------------------------------------------------
extern "C" void kernel_launch(void* const* d_in, const int* in_sizes, int n_in,
                              void* d_out, int out_size)
{
    const float* x      = (const float*)d_in[0];
    const float* W_in   = (const float*)d_in[1];
    const float* W_out  = (const float*)d_in[2];
    const float* conv_w = (const float*)d_in[3];
    const float* conv_b = (const float*)d_in[4];
    const float* dt_w   = (const float*)d_in[5];
    const float* dt_b   = (const float*)d_in[6];
    const float* Aw     = (const float*)d_in[7];
    const float* Dp     = (const float*)d_in[8];
    float* out = (float*)d_out;

    float *p_xz, *p_dt;
    fp16 *p_xh, *p_xl, *p_wi, *p_dw, *p_wo, *p_xch, *p_xcl, *p_yh, *p_yl;
    cudaGetSymbolAddress((void**)&p_xz, g_xz);
    cudaGetSymbolAddress((void**)&p_dt, g_dt);
    cudaGetSymbolAddress((void**)&p_xh, g_xh);
    cudaGetSymbolAddress((void**)&p_xl, g_xl);
    cudaGetSymbolAddress((void**)&p_wi, g_wi);
    cudaGetSymbolAddress((void**)&p_dw, g_dw);
    cudaGetSymbolAddress((void**)&p_wo, g_wo);
    cudaGetSymbolAddress((void**)&p_xch, g_xch);
    cudaGetSymbolAddress((void**)&p_xcl, g_xcl);
    cudaGetSymbolAddress((void**)&p_yh, g_yh);
    cudaGetSymbolAddress((void**)&p_yl, g_yl);

    cudaFuncSetAttribute(f16_gemm<0>, cudaFuncAttributeMaxDynamicSharedMemorySize, GEMM_SMEM);
    cudaFuncSetAttribute(f16_gemm<1>, cudaFuncAttributeMaxDynamicSharedMemorySize, GEMM_SMEM);

    // 1) fused fp16 splits (x -> 2 limbs; weights -> 1 limb)
    split_all_kernel<<<(NSPLIT4_ + 255) / 256, 256>>>(x, W_in, dt_w, W_out);

    // 2) in_proj: xz[M,3072] = x @ W_in^T   (2-product fp16 mma)
    f16_gemm<0><<<dim3((2 * DIN_) / 128, M_ / 128), 256, GEMM_SMEM>>>(
        p_xh, p_xl, p_wi, p_xz, nullptr, M_, 2 * DIN_, DIM_);

    // 3) depthwise conv3 + bias + SiLU (+ split)
    conv_silu_kernel<<<(M_ * DIN_) / 256, 256>>>(conv_w, conv_b);

    // 4) dt = softplus(x_conv @ dt_w^T + dt_b)  <- launch slot 4: ncu target
    f16_gemm<1><<<dim3(DIN_ / 128, M_ / 128), 256, GEMM_SMEM>>>(
        p_xch, p_xcl, p_dw, p_dt, dt_b, M_, DIN_, DIN_);

    // 5) chunked cumsum scan + gating (y written as fp16 limbs)
    scan_phase1<<<dim3(NCHUNK_, B_ * (DIN_ / 256)), 256>>>(Aw);
    scan_phase2<<<(B_ * DIN_) / 256, 256>>>();
    scan_phase3<<<dim3(NCHUNK_, B_ * (DIN_ / 256)), 256>>>(Aw, Dp);

    // 6) out_proj: out[M,1024] = y @ W_out^T
    f16_gemm<0><<<dim3(DIM_ / 128, M_ / 128), 256, GEMM_SMEM>>>(
        p_yh, p_yl, p_wo, out, nullptr, M_, DIM_, DIN_);
}

// round 17
// speedup vs baseline: 6.0108x; 1.5778x over previous
#include <cuda_runtime.h>
#include <cuda_fp16.h>
#include <math.h>
#include <stdint.h>

#define DIM_  1024
#define DIN_  1536
#define B_    4
#define L_    4096
#define M_    (B_ * L_)          // 16384
#define NCHUNK_ 32
#define CHUNK_  (L_ / NCHUNK_)   // 128

typedef __half fp16;

// ---------------- static scratch (no allocations allowed) ----------------
__device__ __align__(16) float g_xz[(size_t)M_ * 2 * DIN_];   // in_proj out [M,3072]
__device__ __align__(16) float g_xcf[(size_t)M_ * DIN_];      // silu(conv) fp32 (scan)
__device__ __align__(16) fp16  g_xcq[(size_t)M_ * DIN_];      // silu(conv) fp16 (gemm A)
__device__ __align__(16) float g_dt[(size_t)M_ * DIN_];
__device__ __align__(16) fp16  g_yq[(size_t)M_ * DIN_];       // y fp16 (gemm A)
__device__ __align__(16) fp16  g_xq[(size_t)M_ * DIM_];       // x fp16 (gemm A)
__device__ __align__(16) fp16  g_wi[(size_t)2 * DIN_ * DIM_]; // weights fp16
__device__ __align__(16) fp16  g_dw[(size_t)DIN_ * DIN_];
__device__ __align__(16) fp16  g_wo[(size_t)DIM_ * DIN_];
__device__ float g_csum[B_ * NCHUNK_ * DIN_];
__device__ float g_cpre[B_ * NCHUNK_ * DIN_];

__device__ __forceinline__ float softplus_f(float v) {
    return v > 20.f ? v : log1pf(expf(v));
}
__device__ __forceinline__ float silu_f(float v) {
    return v / (1.f + expf(-v));
}

// ======================= PTX helpers (base sm_90+/sm_103, no 'a' features) ===
__device__ __forceinline__ uint32_t smem_u32(const void* p) {
    uint32_t a;
    asm("{ .reg .u64 t; cvta.to.shared.u64 t, %1; cvt.u32.u64 %0, t; }" : "=r"(a) : "l"(p));
    return a;
}
#define CP16(saddr, gptr) \
    asm volatile("cp.async.cg.shared.global [%0], [%1], 16;" :: "r"(saddr), "l"(gptr))

#define MBAR_INIT(addr, cnt) \
    asm volatile("mbarrier.init.shared.b64 [%0], %1;" :: "r"(addr), "r"(cnt) : "memory")
#define MBAR_ARRIVE(addr) \
    asm volatile("mbarrier.arrive.shared.b64 _, [%0];" :: "r"(addr) : "memory")
// arrive on mbar when all of this thread's prior cp.asyncs have completed
#define CPA_ARRIVE(addr) \
    asm volatile("cp.async.mbarrier.arrive.noinc.shared.b64 [%0];" :: "r"(addr) : "memory")
#define MBAR_WAIT(addr, ph) do {                                                   \
    uint32_t _m = (addr); uint32_t _p = (ph); uint32_t _d;                         \
    asm volatile("{ .reg .pred p; mbarrier.try_wait.parity.acquire.cta.shared::cta.b64 p, [%1], %2; selp.b32 %0,1,0,p; }" \
        : "=r"(_d) : "r"(_m), "r"(_p) : "memory");                                 \
    if (!_d) {                                                                     \
        asm volatile("{ .reg .pred P1; WL%=: mbarrier.try_wait.parity.acquire.cta.shared::cta.b64 P1, [%0], %1, 0x989680; @P1 bra.uni WD%=; bra.uni WL%=; WD%=: }" \
            :: "r"(_m), "r"(_p) : "memory");                                       \
    } } while (0)

#define LDSM4(r, a) \
    asm volatile("ldmatrix.sync.aligned.m8n8.x4.shared.b16 {%0,%1,%2,%3}, [%4];" \
        : "=r"((r)[0]), "=r"((r)[1]), "=r"((r)[2]), "=r"((r)[3]) : "r"(a))

#define MMA_F16(d, a, b0v, b1v) \
    asm volatile("mma.sync.aligned.m16n8k16.row.col.f32.f16.f16.f32 " \
        "{%0,%1,%2,%3}, {%4,%5,%6,%7}, {%8,%9}, {%0,%1,%2,%3};" \
        : "+f"((d)[0]), "+f"((d)[1]), "+f"((d)[2]), "+f"((d)[3]) \
        : "r"((a)[0]), "r"((a)[1]), "r"((a)[2]), "r"((a)[3]), "r"(b0v), "r"(b1v))

__device__ __forceinline__ uint32_t sw64(uint32_t off) {
    return off ^ ((off >> 3) & 0x30);
}

// ============== single-product fp16 mma.sync GEMM, 2-stage mbarrier pipeline =
// C[m,n] = sum_k A[m,k] * B[n,k], both fp16 K-contiguous, fp32 accumulate.
// Block 128x128, BK=32, 256 threads (8 warps: 2 M x 4 N, warp tile 64x32).
// 2-stage ping-pong (fully unrolled stage addressing).
#define BK_      32
#define STAGE_B  16384          // A 8K | B 8K
#define B_OFF    8192
#define GEMM_SMEM (2 * STAGE_B)   // 32 KB

__device__ __forceinline__ void load_stage(
    uint32_t sb, const fp16* __restrict__ A, const fp16* __restrict__ Bw,
    int row0, int col0, int k0, int K, int tid)
{
#pragma unroll
    for (int i = 0; i < 2; ++i) {
        const int idx = tid + i * 256;          // 0..511
        const int r  = idx >> 2;                // 0..127
        const int kg = idx & 3;                 // 16B group along K
        const uint32_t so = sw64((uint32_t)(r * 64 + kg * 16));
        const size_t ga = (size_t)(row0 + r) * K + k0 + kg * 8;
        const size_t gb = (size_t)(col0 + r) * K + k0 + kg * 8;
        CP16(sb + so,         A  + ga);
        CP16(sb + B_OFF + so, Bw + gb);
    }
}

// MODE 0: plain store.  MODE 1: softplus(acc + bias[n]).
template <int MODE>
__global__ void __launch_bounds__(256, 2)
f16_gemm(const fp16* __restrict__ A, const fp16* __restrict__ Bw,
         float* __restrict__ C, const float* __restrict__ bias,
         int M, int N, int K)
{
    extern __shared__ char smem_raw[];
    __shared__ __align__(8) uint64_t s_mbar[4];   // full0, full1, empty0, empty1
    const uint32_t smb = smem_u32(smem_raw);
    const int tid  = threadIdx.x;
    const int lane = tid & 31;
    const int wid  = tid >> 5;
    const int wm   = (wid >> 2) * 64;   // warp M base within block
    const int wn   = (wid & 3) * 32;    // warp N base within block
    const int row0 = blockIdx.y * 128;
    const int col0 = blockIdx.x * 128;
    const int nch  = K / BK_;           // even for all three GEMMs

    if (tid == 0) {
        MBAR_INIT(smem_u32(&s_mbar[0]), 256);
        MBAR_INIT(smem_u32(&s_mbar[1]), 256);
        MBAR_INIT(smem_u32(&s_mbar[2]), 256);
        MBAR_INIT(smem_u32(&s_mbar[3]), 256);
    }
    __syncthreads();
    const uint32_t mbf0 = smem_u32(&s_mbar[0]);
    const uint32_t mbf1 = smem_u32(&s_mbar[1]);
    const uint32_t mbe0 = smem_u32(&s_mbar[2]);
    const uint32_t mbe1 = smem_u32(&s_mbar[3]);

    float acc[4][4][4];
#pragma unroll
    for (int i = 0; i < 4; ++i)
#pragma unroll
        for (int j = 0; j < 4; ++j)
#pragma unroll
            for (int t = 0; t < 4; ++t) acc[i][j][t] = 0.f;

    // prologue: fill both stages (stages start empty, no wait needed)
    load_stage(smb, A, Bw, row0, col0, 0, K, tid);
    CPA_ARRIVE(mbf0);
    load_stage(smb + STAGE_B, A, Bw, row0, col0, BK_, K, tid);
    CPA_ARRIVE(mbf1);

    // hoisted per-lane ldmatrix tile-local swizzled offsets
    const int a_row = (lane & 7) + ((lane >> 3) & 1) * 8;
    const int a_kof = ((lane >> 4) & 1) * 16;
    const int b_row = (lane & 7) + ((lane >> 4) & 1) * 8;
    const int b_kof = ((lane >> 3) & 1) * 16;
    uint32_t offA[2][4], offB[2][2];
#pragma unroll
    for (int ks = 0; ks < 2; ++ks) {
#pragma unroll
        for (int mt = 0; mt < 4; ++mt)
            offA[ks][mt] =
                sw64((uint32_t)((wm + mt * 16 + a_row) * 64 + ks * 32 + a_kof));
#pragma unroll
        for (int np = 0; np < 2; ++np)
            offB[ks][np] = B_OFF +
                sw64((uint32_t)((wn + np * 16 + b_row) * 64 + ks * 32 + b_kof));
    }

    const int T = nch >> 1;
    for (int t = 0; t < T; ++t) {
        const uint32_t par = (uint32_t)(t & 1);
#pragma unroll
        for (int h = 0; h < 2; ++h) {
            const uint32_t sb  = smb + h * STAGE_B;
            const uint32_t mbf = h ? mbf1 : mbf0;
            const uint32_t mbe = h ? mbe1 : mbe0;

            MBAR_WAIT(mbf, par);   // all threads' copies for this stage landed
#pragma unroll
            for (int ks = 0; ks < 2; ++ks) {
                uint32_t fB[2][4];
#pragma unroll
                for (int np = 0; np < 2; ++np)
                    LDSM4(fB[np], sb + offB[ks][np]);
#pragma unroll
                for (int mt = 0; mt < 4; ++mt) {
                    uint32_t fA[4];
                    LDSM4(fA, sb + offA[ks][mt]);
                    // last LDSM of this stage -> signal "stage read complete"
                    if (ks == 1 && mt == 3) MBAR_ARRIVE(mbe);
#pragma unroll
                    for (int nt = 0; nt < 4; ++nt) {
                        const int np = nt >> 1, rr = (nt & 1) * 2;
                        MMA_F16(acc[mt][nt], fA, fB[np][rr], fB[np][rr + 1]);
                    }
                }
            }
            if (t < T - 1) {
                // overwrite guard: waits only for all warps' LDSM of THIS stage
                MBAR_WAIT(mbe, par);
                load_stage(sb, A, Bw, row0, col0, (2 * t + h + 2) * BK_, K, tid);
                CPA_ARRIVE(mbf);
            }
        }
    }

    // epilogue: direct float2 stores
#pragma unroll
    for (int mt = 0; mt < 4; ++mt) {
        const int r0 = row0 + wm + mt * 16 + (lane >> 2);
#pragma unroll
        for (int nt = 0; nt < 4; ++nt) {
            const int cc = col0 + wn + nt * 8 + (lane & 3) * 2;
            float v0 = acc[mt][nt][0], v1 = acc[mt][nt][1];
            float v2 = acc[mt][nt][2], v3 = acc[mt][nt][3];
            if (MODE == 1) {
                const float b0 = __ldg(&bias[cc]), b1 = __ldg(&bias[cc + 1]);
                v0 = softplus_f(v0 + b0); v1 = softplus_f(v1 + b1);
                v2 = softplus_f(v2 + b0); v3 = softplus_f(v3 + b1);
            }
            *(float2*)&C[(size_t)r0 * N + cc]       = make_float2(v0, v1);
            *(float2*)&C[(size_t)(r0 + 8) * N + cc] = make_float2(v2, v3);
        }
    }
}

// ---------------- fused fp32 -> fp16 conversion of all four sources --------
#define N0_ (M_ * DIM_)            // x
#define N1_ (2 * DIN_ * DIM_)      // W_in
#define N2_ (DIN_ * DIN_)          // dt_w
#define N3_ (DIM_ * DIN_)          // W_out
#define NSPLIT4_ ((N0_ + N1_ + N2_ + N3_) / 4)

__device__ __forceinline__ void cvt4_store(const float4 v, fp16* dst, int i4)
{
    ushort4 w = make_ushort4(
        __half_as_ushort(__float2half_rn(v.x)), __half_as_ushort(__float2half_rn(v.y)),
        __half_as_ushort(__float2half_rn(v.z)), __half_as_ushort(__float2half_rn(v.w)));
    *(ushort4*)&dst[i4 * 4] = w;
}

__global__ void __launch_bounds__(256)
split_all_kernel(const float* __restrict__ x, const float* __restrict__ W_in,
                 const float* __restrict__ dt_w, const float* __restrict__ W_out)
{
    int i = blockIdx.x * blockDim.x + threadIdx.x;
    if (i >= NSPLIT4_) return;
    if (i < N0_ / 4) {
        cvt4_store(*(const float4*)&x[i * 4], g_xq, i);
    } else if (i < (N0_ + N1_) / 4) {
        int j = i - N0_ / 4;
        cvt4_store(*(const float4*)&W_in[j * 4], g_wi, j);
    } else if (i < (N0_ + N1_ + N2_) / 4) {
        int j = i - (N0_ + N1_) / 4;
        cvt4_store(*(const float4*)&dt_w[j * 4], g_dw, j);
    } else {
        int j = i - (N0_ + N1_ + N2_) / 4;
        cvt4_store(*(const float4*)&W_out[j * 4], g_wo, j);
    }
}

// -------- depthwise conv3 (pad=1) + bias + SiLU; fp32 for scan, fp16 for GEMM
__global__ void __launch_bounds__(256)
conv_silu_kernel(const float* __restrict__ cw, const float* __restrict__ cb)
{
    int idx = blockIdx.x * blockDim.x + threadIdx.x;  // over M_*DIN_
    int c  = idx % DIN_;
    int bl = idx / DIN_;
    int l  = bl % L_;
    const float* base = g_xz + (size_t)bl * (2 * DIN_) + c;
    float x0 = base[0];
    float xm = (l > 0)      ? base[-(2 * DIN_)] : 0.f;
    float xp = (l < L_ - 1) ? base[ (2 * DIN_)] : 0.f;
    float w0 = __ldg(&cw[c * 3 + 0]);
    float w1 = __ldg(&cw[c * 3 + 1]);
    float w2 = __ldg(&cw[c * 3 + 2]);
    float v = fmaf(w0, xm, fmaf(w1, x0, fmaf(w2, xp, __ldg(&cb[c]))));
    v = silu_f(v);
    g_xcf[idx] = v;
    g_xcq[idx] = __float2half_rn(v);
}

// ---------------- scan phase 1: per-chunk sums only -----------------------
__global__ void __launch_bounds__(256)
scan_phase1(const float* __restrict__ Aw)
{
    const int ct = blockIdx.y % (DIN_ / 256);
    const int b  = blockIdx.y / (DIN_ / 256);
    const int ch = blockIdx.x;
    const int c  = ct * 256 + threadIdx.x;
    const float Ac = __ldg(&Aw[c]);
    size_t base = ((size_t)b * L_ + (size_t)ch * CHUNK_) * DIN_ + c;
    float sum = 0.f;
#pragma unroll 4
    for (int i = 0; i < CHUNK_; i++) {
        size_t off = base + (size_t)i * DIN_;
        float dt = g_dt[off];
        float xc = g_xcf[off];
        sum += xc * dt * expf(Ac * dt);
    }
    g_csum[((size_t)b * NCHUNK_ + ch) * DIN_ + c] = sum;
}

// ---------------- scan phase 2: exclusive prefix over chunks --------------
__global__ void __launch_bounds__(256)
scan_phase2()
{
    int idx = blockIdx.x * blockDim.x + threadIdx.x;  // over B_*DIN_
    int c = idx % DIN_;
    int b = idx / DIN_;
    float run = 0.f;
    for (int ch = 0; ch < NCHUNK_; ch++) {
        size_t o = ((size_t)b * NCHUNK_ + ch) * DIN_ + c;
        float v = g_csum[o];
        g_cpre[o] = run;
        run += v;
    }
}

// ---------------- scan phase 3: recompute ae, gate, write fp16 y ----------
__global__ void __launch_bounds__(256)
scan_phase3(const float* __restrict__ Aw, const float* __restrict__ Dp)
{
    const int ct = blockIdx.y % (DIN_ / 256);
    const int b  = blockIdx.y / (DIN_ / 256);
    const int ch = blockIdx.x;
    const int c  = ct * 256 + threadIdx.x;
    const float Ac = __ldg(&Aw[c]);
    const float Dc = __ldg(&Dp[c]);
    float run = g_cpre[((size_t)b * NCHUNK_ + ch) * DIN_ + c];
    size_t base  = ((size_t)b * L_ + (size_t)ch * CHUNK_) * DIN_ + c;
    size_t zbase = ((size_t)b * L_ + (size_t)ch * CHUNK_) * (2 * DIN_) + DIN_ + c;
#pragma unroll 4
    for (int i = 0; i < CHUNK_; i++) {
        size_t off = base + (size_t)i * DIN_;
        float dt = g_dt[off];
        float xc = g_xcf[off];
        float ae = expf(Ac * dt);   // bit-identical to phase 1's value
        run += xc * dt * ae;
        float y  = run * ae + xc * Dc;
        float z  = g_xz[zbase + (size_t)i * (2 * DIN_)];
        y *= silu_f(z);
        g_yq[off] = __float2half_rn(y);
    }
}

// ---------------------------------------------------------------------------
extern "C" void kernel_launch(void* const* d_in, const int* in_sizes, int n_in,
                              void* d_out, int out_size)
{
    const float* x      = (const float*)d_in[0];
    const float* W_in   = (const float*)d_in[1];
    const float* W_out  = (const float*)d_in[2];
    const float* conv_w = (const float*)d_in[3];
    const float* conv_b = (const float*)d_in[4];
    const float* dt_w   = (const float*)d_in[5];
    const float* dt_b   = (const float*)d_in[6];
    const float* Aw     = (const float*)d_in[7];
    const float* Dp     = (const float*)d_in[8];
    float* out = (float*)d_out;

    float *p_xz, *p_dt;
    fp16 *p_xq, *p_wi, *p_dw, *p_wo, *p_xcq, *p_yq;
    cudaGetSymbolAddress((void**)&p_xz, g_xz);
    cudaGetSymbolAddress((void**)&p_dt, g_dt);
    cudaGetSymbolAddress((void**)&p_xq, g_xq);
    cudaGetSymbolAddress((void**)&p_wi, g_wi);
    cudaGetSymbolAddress((void**)&p_dw, g_dw);
    cudaGetSymbolAddress((void**)&p_wo, g_wo);
    cudaGetSymbolAddress((void**)&p_xcq, g_xcq);
    cudaGetSymbolAddress((void**)&p_yq, g_yq);

    cudaFuncSetAttribute(f16_gemm<0>, cudaFuncAttributeMaxDynamicSharedMemorySize, GEMM_SMEM);
    cudaFuncSetAttribute(f16_gemm<1>, cudaFuncAttributeMaxDynamicSharedMemorySize, GEMM_SMEM);

    // 1) fused fp16 conversions (x, W_in, dt_w, W_out)
    split_all_kernel<<<(NSPLIT4_ + 255) / 256, 256>>>(x, W_in, dt_w, W_out);

    // 2) in_proj: xz[M,3072] = x @ W_in^T   (single-product fp16 mma)
    f16_gemm<0><<<dim3((2 * DIN_) / 128, M_ / 128), 256, GEMM_SMEM>>>(
        p_xq, p_wi, p_xz, nullptr, M_, 2 * DIN_, DIM_);

    // 3) depthwise conv3 + bias + SiLU (fp32 + fp16 outputs)
    conv_silu_kernel<<<(M_ * DIN_) / 256, 256>>>(conv_w, conv_b);

    // 4) dt = softplus(x_conv @ dt_w^T + dt_b)  <- launch slot 4: ncu target
    f16_gemm<1><<<dim3(DIN_ / 128, M_ / 128), 256, GEMM_SMEM>>>(
        p_xcq, p_dw, p_dt, dt_b, M_, DIN_, DIN_);

    // 5) chunked cumsum scan + gating (y written as fp16)
    scan_phase1<<<dim3(NCHUNK_, B_ * (DIN_ / 256)), 256>>>(Aw);
    scan_phase2<<<(B_ * DIN_) / 256, 256>>>();
    scan_phase3<<<dim3(NCHUNK_, B_ * (DIN_ / 256)), 256>>>(Aw, Dp);

    // 6) out_proj: out[M,1024] = y @ W_out^T
    f16_gemm<0><<<dim3(DIM_ / 128, M_ / 128), 256, GEMM_SMEM>>>(
        p_yq, p_wo, out, nullptr, M_, DIM_, DIN_);
}